// round 13
// baseline (speedup 1.0000x reference)
#include <cuda_runtime.h>
#include <cuda_bf16.h>
#include <cstdint>

// out[t][o] = sum_h R[t][h] * W[o][h],  R = x @ basis^T, W = amp*cos(phase)
// Step 2 (R): mma.m16n8k8 TF32, 3-stage cp.async ring (2 chunks in flight).
// Step 3 (out): mma.m16n8k8 TF32; epilogue = xor1-shuffle half-transpose
//               -> direct STG.128 (no smem staging round-trip).
#define TOKENS 16384
#define INF    1024
#define HARM   32
#define OUTF   4096

__device__ __align__(16) float g_R[TOKENS * HARM];   // 2 MB
__device__ __align__(16) float g_W[OUTF * HARM];     // 512 KB

__device__ __forceinline__ uint32_t smem_u32(const void* p) {
    uint32_t a;
    asm("{ .reg .u64 t; cvta.to.shared.u64 t, %1; cvt.u32.u64 %0, t; }"
        : "=r"(a) : "l"(p));
    return a;
}
__device__ __forceinline__ float tf32_rna(float v) {
    float r;
    asm("cvt.rna.tf32.f32 %0, %1;" : "=f"(r) : "f"(v));
    return r;
}
__device__ __forceinline__ uint32_t tf32_r(uint32_t v) {
    uint32_t r;
    asm("cvt.rna.tf32.f32 %0, %1;" : "=r"(r) : "r"(v));
    return r;
}
#define CPA16(dst, src) \
    asm volatile("cp.async.cg.shared.global [%0], [%1], 16;" \
                 :: "r"(dst), "l"(src) : "memory")
#define CPA_COMMIT() asm volatile("cp.async.commit_group;" ::: "memory")
#define CPA_WAIT2()  asm volatile("cp.async.wait_group 2;" ::: "memory")
#define CPA_WAIT1()  asm volatile("cp.async.wait_group 1;" ::: "memory")
#define CPA_WAIT0()  asm volatile("cp.async.wait_group 0;" ::: "memory")

// ---------------------------------------------------------------------------
// Step 2 (+W prep): CTAs [0,256) R = x @ basis^T (TF32 mma, 3-stage ring).
// CTAs [256,288): W = tf32(amp*cos(phase)).
// ---------------------------------------------------------------------------
#define XPITCH 68
#define SX_BYTES (64 * XPITCH * 4)    // 17408
#define SB_BYTES (32 * XPITCH * 4)    // 8704
#define STG_BYTES (SX_BYTES + SB_BYTES)          // 26112 per stage
#define SMR_TOTAL (3 * STG_BYTES)                // 78336

__global__ __launch_bounds__(128) void resonance_tf32_kernel(
    const float* __restrict__ x, const float* __restrict__ basis,
    const float* __restrict__ phase, const float* __restrict__ amp) {
    if (blockIdx.x >= 256) {
        int base = (blockIdx.x - 256) * 4096;
#pragma unroll
        for (int r = 0; r < 32; r++) {
            int idx = base + threadIdx.x + r * 128;
            g_W[idx] = tf32_rna(amp[idx] * cosf(phase[idx]));
        }
        return;
    }

    extern __shared__ char smem[];
    uint32_t sbase = smem_u32(smem);

    int tid  = threadIdx.x;
    int lane = tid & 31;
    int wid  = tid >> 5;
    int tb   = blockIdx.x * 64;

    auto issue_chunk = [&](int ck) {
        int s = ck % 3;
        uint32_t sx = sbase + (uint32_t)s * STG_BYTES;
        uint32_t sb = sx + SX_BYTES;
        const float* xsrc = x + (long)ck * 64;
        const float* bsrc = basis + ck * 64;
#pragma unroll
        for (int r = 0; r < 8; r++) {
            int q = tid + r * 128;
            int row = q >> 4, c4 = q & 15;
            CPA16(sx + (uint32_t)row * (XPITCH * 4) + c4 * 16,
                  xsrc + (long)(tb + row) * INF + c4 * 4);
        }
#pragma unroll
        for (int r = 0; r < 4; r++) {
            int q = tid + r * 128;
            int row = q >> 4, c4 = q & 15;
            CPA16(sb + (uint32_t)row * (XPITCH * 4) + c4 * 16,
                  bsrc + (long)row * INF + c4 * 4);
        }
        CPA_COMMIT();
    };

    float acc[4][4];
#pragma unroll
    for (int j = 0; j < 4; j++)
#pragma unroll
        for (int c = 0; c < 4; c++) acc[j][c] = 0.0f;

    issue_chunk(0);
    issue_chunk(1);
    issue_chunk(2);

    for (int ck = 0; ck < 16; ck++) {
        int s = ck % 3;
        // Retire chunk ck: outstanding after = remaining in-flight prefetches.
        if (ck < 14) CPA_WAIT2();
        else if (ck == 14) CPA_WAIT1();
        else CPA_WAIT0();
        __syncthreads();

        uint32_t sx_b = sbase + (uint32_t)s * STG_BYTES;
        uint32_t sb_b = sx_b + SX_BYTES;

#pragma unroll
        for (int ks = 0; ks < 8; ks++) {
            uint32_t af[4];
            {
                int row = wid * 16 + (lane & 15);
                uint32_t ao = sx_b + (uint32_t)row * (XPITCH * 4) + ks * 32 + (lane >> 4) * 16;
                asm volatile(
                    "ldmatrix.sync.aligned.m8n8.x4.shared.b16 {%0,%1,%2,%3}, [%4];"
                    : "=r"(af[0]), "=r"(af[1]), "=r"(af[2]), "=r"(af[3])
                    : "r"(ao));
#pragma unroll
                for (int c = 0; c < 4; c++) af[c] = tf32_r(af[c]);
            }
#pragma unroll
            for (int j = 0; j < 4; j++) {
                int nrow = j * 8 + (lane & 7);
                uint32_t bo = sb_b + (uint32_t)nrow * (XPITCH * 4) + ks * 32 + ((lane >> 3) & 1) * 16;
                uint32_t bf[2];
                asm volatile(
                    "ldmatrix.sync.aligned.m8n8.x2.shared.b16 {%0,%1}, [%2];"
                    : "=r"(bf[0]), "=r"(bf[1]) : "r"(bo));
                bf[0] = tf32_r(bf[0]);
                bf[1] = tf32_r(bf[1]);
                asm volatile(
                    "mma.sync.aligned.m16n8k8.row.col.f32.tf32.tf32.f32 "
                    "{%0,%1,%2,%3}, {%4,%5,%6,%7}, {%8,%9}, {%0,%1,%2,%3};"
                    : "+f"(acc[j][0]), "+f"(acc[j][1]), "+f"(acc[j][2]), "+f"(acc[j][3])
                    : "r"(af[0]), "r"(af[1]), "r"(af[2]), "r"(af[3]),
                      "r"(bf[0]), "r"(bf[1]));
            }
        }

        __syncthreads();       // stage s free for the ck+3 prefetch
        if (ck + 3 < 16) issue_chunk(ck + 3);
    }

    int qrow = lane >> 2;
    int qcol = (lane & 3) * 2;
#pragma unroll
    for (int j = 0; j < 4; j++) {
#pragma unroll
        for (int hh = 0; hh < 2; hh++) {
            long t = tb + wid * 16 + qrow + hh * 8;
            float v0 = tf32_rna(acc[j][hh * 2 + 0]);
            float v1 = tf32_rna(acc[j][hh * 2 + 1]);
            *reinterpret_cast<float2*>(&g_R[t * HARM + j * 8 + qcol]) =
                make_float2(v0, v1);
        }
    }
}

// ---------------------------------------------------------------------------
// Step 3: out = R @ W^T via mma.m16n8k8 TF32, K=32 single term.
// CTA 128 tokens x 256 outputs (2 B-subtiles up-front). 8 warps 2(m)x4(n).
// Epilogue: xor1 shuffle merges col-pairs into float4s -> direct STG.128.
//   q=lane&3: q0 stores cols 8j (j=0,1), q1: 8j (j=2,3),
//             q2: 8j+4 (j=0,1), q3: 8j+4 (j=2,3).
// ---------------------------------------------------------------------------
#define TPITCH 36
#define TILE_BYTES (128 * TPITCH * 4)       // 18432
#define SM3_TOTAL (3 * TILE_BYTES)          // 55296
#define NBT 2

__global__ __launch_bounds__(256, 2) void holo_tf32_kernel(float* __restrict__ out) {
    extern __shared__ char smem[];
    char* sA = smem;

    int tid  = threadIdx.x;
    int lane = tid & 31;
    int wid  = tid >> 5;
    int warp_m = wid >> 2;   // 0..1
    int warp_n = wid & 3;    // 0..3

    int ob0 = blockIdx.x * 256;
    int tb  = blockIdx.y * 128;

    const float4* gA = reinterpret_cast<const float4*>(&g_R[(long)tb * HARM]);
    const float4* gB = reinterpret_cast<const float4*>(&g_W[(long)ob0 * HARM]);

#pragma unroll
    for (int r = 0; r < 4; r++) {
        int q = tid + r * 256;        // 0..1023
        int row = q >> 3, ch = q & 7;
        uint32_t soff = (uint32_t)row * (TPITCH * 4) + ch * 16;
        *reinterpret_cast<float4*>(sA + soff) = gA[q];
        *reinterpret_cast<float4*>(sA + TILE_BYTES + soff) = gB[q];
        *reinterpret_cast<float4*>(sA + 2 * TILE_BYTES + soff) = gB[1024 + q];
    }
    __syncthreads();

    uint32_t sAb = smem_u32(sA);
    int qrow = lane >> 2;
    int q    = lane & 3;
    int qhi  = q >> 1;            // 0,0,1,1
    int qlo  = q & 1;             // 0,1,0,1

#pragma unroll
    for (int nb = 0; nb < NBT; nb++) {
        uint32_t sBb = sAb + TILE_BYTES + (uint32_t)nb * TILE_BYTES;

        float acc[4][4][4];
#pragma unroll
        for (int i = 0; i < 4; i++)
#pragma unroll
            for (int j = 0; j < 4; j++)
#pragma unroll
                for (int c = 0; c < 4; c++) acc[i][j][c] = 0.0f;

#pragma unroll
        for (int ks = 0; ks < 4; ks++) {
            uint32_t af[4][4];
#pragma unroll
            for (int i = 0; i < 4; i++) {
                int row = warp_m * 64 + i * 16 + (lane & 15);
                uint32_t addr = sAb + (uint32_t)row * (TPITCH * 4) + ks * 32 + (lane >> 4) * 16;
                asm volatile(
                    "ldmatrix.sync.aligned.m8n8.x4.shared.b16 {%0,%1,%2,%3}, [%4];"
                    : "=r"(af[i][0]), "=r"(af[i][1]), "=r"(af[i][2]), "=r"(af[i][3])
                    : "r"(addr));
            }
            uint32_t bf[4][2];
#pragma unroll
            for (int j = 0; j < 4; j++) {
                int orow = warp_n * 32 + j * 8 + (lane & 7);
                uint32_t addr = sBb + (uint32_t)orow * (TPITCH * 4) + ks * 32 + ((lane >> 3) & 1) * 16;
                asm volatile(
                    "ldmatrix.sync.aligned.m8n8.x2.shared.b16 {%0,%1}, [%2];"
                    : "=r"(bf[j][0]), "=r"(bf[j][1])
                    : "r"(addr));
            }
#pragma unroll
            for (int i = 0; i < 4; i++)
#pragma unroll
                for (int j = 0; j < 4; j++) {
                    asm volatile(
                        "mma.sync.aligned.m16n8k8.row.col.f32.tf32.tf32.f32 "
                        "{%0,%1,%2,%3}, {%4,%5,%6,%7}, {%8,%9}, {%0,%1,%2,%3};"
                        : "+f"(acc[i][j][0]), "+f"(acc[i][j][1]),
                          "+f"(acc[i][j][2]), "+f"(acc[i][j][3])
                        : "r"(af[i][0]), "r"(af[i][1]), "r"(af[i][2]), "r"(af[i][3]),
                          "r"(bf[j][0]), "r"(bf[j][1]));
                }
        }

        // Shuffle epilogue: per (i, half): bfly xor1 -> float4 chunks -> STG.128.
#pragma unroll
        for (int i = 0; i < 4; i++) {
#pragma unroll
            for (int h = 0; h < 2; h++) {
                float r0[4], r1[4];
#pragma unroll
                for (int j = 0; j < 4; j++) {
                    r0[j] = __shfl_xor_sync(0xffffffffu, acc[i][j][2 * h], 1);
                    r1[j] = __shfl_xor_sync(0xffffffffu, acc[i][j][2 * h + 1], 1);
                }
                long row = tb + warp_m * 64 + i * 16 + qrow + 8 * h;
                long cb  = ob0 + nb * 128 + warp_n * 32 + 4 * qhi;
#pragma unroll
                for (int t = 0; t < 2; t++) {
                    // j = 2*qlo + t, selected via ternaries (const reg indices)
                    float o0 = qlo ? acc[i][2 + t][2 * h]     : acc[i][t][2 * h];
                    float o1 = qlo ? acc[i][2 + t][2 * h + 1] : acc[i][t][2 * h + 1];
                    float p0 = qlo ? r0[2 + t] : r0[t];
                    float p1 = qlo ? r1[2 + t] : r1[t];
                    // even q: (own, partner); odd q: (partner, own)
                    float4 v = (q & 1)
                        ? make_float4(p0, p1, o0, o1)
                        : make_float4(o0, o1, p0, p1);
                    long col = cb + 8 * (2 * qlo + t);
                    __stcs(reinterpret_cast<float4*>(&out[row * OUTF + col]), v);
                }
            }
        }
    }
}

// ---------------------------------------------------------------------------
extern "C" void kernel_launch(void* const* d_in, const int* in_sizes, int n_in,
                              void* d_out, int out_size) {
    const float* x     = (const float*)d_in[0];  // [16384,1024]
    const float* basis = (const float*)d_in[1];  // [32,1024]
    const float* phase = (const float*)d_in[2];  // [4096,32]
    const float* amp   = (const float*)d_in[3];  // [4096,32]
    float* out = (float*)d_out;                  // [16384,4096]

    cudaFuncSetAttribute(resonance_tf32_kernel,
                         cudaFuncAttributeMaxDynamicSharedMemorySize, SMR_TOTAL);
    cudaFuncSetAttribute(holo_tf32_kernel,
                         cudaFuncAttributeMaxDynamicSharedMemorySize, SM3_TOTAL);

    resonance_tf32_kernel<<<256 + 32, 128, SMR_TOTAL>>>(x, basis, phase, amp);
    dim3 gridC(OUTF / 256, TOKENS / 128);
    holo_tf32_kernel<<<gridC, 256, SM3_TOTAL>>>(out);
}